// round 9
// baseline (speedup 1.0000x reference)
#include <cuda_runtime.h>
#include <cuda_bf16.h>
#include <math.h>
#include <cstdint>

// ============================================================================
// BiDirectionalSymplecticLayer — fused persistent kernel, 2-CTA/SM edition.
// BM=64 rows per CTA, 256 threads, 2 CTAs co-resident per SM so one CTA's
// MMA phase hides the other's barriers/epilogues. Intermediates (H, G) in
// swizzled smem tiles (64x256); weights stream L2->smem in k32 double-buffered
// chunks (80B rows); ldmatrix.m8n8.x4 fragments; cross-pass weight prefetch.
// ============================================================================

#define D       256
#define FD      128
#define MTOT    16384
#define BHALF   8192
#define DT_MAG  0.1f
#define BM      64
#define NTH     256

// smem layout (bytes)
#define OFF_H   0                       // H tile: 64 x 128 words, swizzled
#define OFF_G   32768                   // G tile (A-staging overlays in pass 1)
#define OFF_AB0 32768                   // A staging buf0: 64 x 80B
#define OFF_AB1 (32768 + 5120)
#define OFF_BB0 65536                   // B staging buf0: 256 x 80B
#define OFF_BB1 (65536 + 20480)
#define OFF_B1S 106496
#define OFF_B2S 107520
#define OFF_WO  108544
#define SMEM_TOTAL 109568

__device__ float         g_S [MTOT * D];
__device__ __nv_bfloat16 g_Sb[MTOT * D];
__device__ __nv_bfloat16 g_W1b [D * D];    // W1  [n][k]
__device__ __nv_bfloat16 g_W2b [D * D];    // W2  [n][k]
__device__ __nv_bfloat16 g_W1Tb[D * D];    // W1^T [n][k]
__device__ __nv_bfloat16 g_W2Tb[D * D];    // W2^T [n][k]

// ------------------------------- helpers ------------------------------------
__device__ __forceinline__ void cpa16(uint32_t dst, const void* src) {
    asm volatile("cp.async.cg.shared.global [%0], [%1], 16;"
                 :: "r"(dst), "l"(src) : "memory");
}
__device__ __forceinline__ uint32_t smem_u32(const void* p) {
    uint32_t r;
    asm("{ .reg .u64 t; cvta.to.shared.u64 t, %1; cvt.u32.u64 %0, t; }"
        : "=r"(r) : "l"(p));
    return r;
}
__device__ __forceinline__ void mma16(float* c, const uint32_t* a, const uint32_t* b) {
    asm volatile(
        "mma.sync.aligned.m16n8k16.row.col.f32.bf16.bf16.f32 "
        "{%0,%1,%2,%3}, {%4,%5,%6,%7}, {%8,%9}, {%0,%1,%2,%3};"
        : "+f"(c[0]), "+f"(c[1]), "+f"(c[2]), "+f"(c[3])
        : "r"(a[0]), "r"(a[1]), "r"(a[2]), "r"(a[3]), "r"(b[0]), "r"(b[1]));
}
#define LDMX4(r, addr) \
    asm volatile("ldmatrix.sync.aligned.m8n8.x4.shared.b16 {%0,%1,%2,%3}, [%4];" \
                 : "=r"((r)[0]), "=r"((r)[1]), "=r"((r)[2]), "=r"((r)[3]) \
                 : "r"(addr))
__device__ __forceinline__ uint32_t pk2(float x, float y) {
    __nv_bfloat162 h = __floats2bfloat162_rn(x, y);
    return *reinterpret_cast<uint32_t*>(&h);
}
__device__ __forceinline__ float2 up2(uint32_t u) {
    __nv_bfloat162 h = *reinterpret_cast<__nv_bfloat162*>(&u);
    return make_float2(__bfloat162float(h.x), __bfloat162float(h.y));
}
__device__ __forceinline__ float ftanh(float x) {
    float e;
    asm("ex2.approx.f32 %0, %1;" : "=f"(e) : "f"(x * 2.885390082f));
    float r;
    asm("rcp.approx.f32 %0, %1;" : "=f"(r) : "f"(e + 1.0f));
    return 1.0f - 2.0f * r;
}

// stage one k32 B chunk (rows x 64B) into an 80B-stride buffer; own group.
__device__ __forceinline__ void stageB_rows(uint32_t sbase, uint32_t dstOff,
                                            const __nv_bfloat16* Bg0, int kc,
                                            int rows, int tid) {
    const __nv_bfloat16* Bg = Bg0 + kc * 32;
    const int n = rows >> 6;                  // rows*4 xfers / 256 threads
    for (int i = 0; i < n; i++) {
        int idx = tid + (i << 8);
        int row = idx >> 2, c = idx & 3;
        cpa16(sbase + dstOff + row * 80 + c * 16, Bg + (size_t)row * D + c * 8);
    }
    asm volatile("cp.async.commit_group;" ::: "memory");
}

// --------------------------- prologue kernel --------------------------------
__global__ void prep_kernel(const float* __restrict__ W1,
                            const float* __restrict__ W2) {
    int idx = blockIdx.x * blockDim.x + threadIdx.x;
    int r = idx >> 8, c = idx & 255;
    __nv_bfloat16 v1 = __float2bfloat16(W1[idx]);
    __nv_bfloat16 v2 = __float2bfloat16(W2[idx]);
    g_W1b[idx] = v1;
    g_W2b[idx] = v2;
    g_W1Tb[c * D + r] = v1;
    g_W2Tb[c * D + r] = v2;
}

// ------------------------------ fused pass ----------------------------------
//  MODE 0: A = staged g_Sb, B = g_W1Tb -> H = tanh(acc + b1)
//  MODE 1: A = H tile,      B = g_W2Tb -> G = wout*(1 - tanh(acc+b2)^2)
//  MODE 2: A = G tile,      B = g_W2b  -> G = acc*(1 - H^2)
//  MODE 3: A = G tile,      B = g_W1b  -> full kick (NT=8)
//  MODE 4: A = G tile,      B = g_W1b  -> half kick (NT=4)
// 8 warps: wm = (wid&1)*32, wn = (wid>>1)*(NT*8). k32 chunks, 16 per pass.
template <int MODE, int NT>
__device__ __forceinline__ void pass_gemm(char* smem, uint32_t sbase,
                                          int m0, float dtv,
                                          const __nv_bfloat16* nextB,
                                          int nextRows) {
    const int tid  = threadIdx.x;
    const int wid  = tid >> 5;
    const int lane = tid & 31;
    const int g    = lane >> 2;
    const int t    = lane & 3;
    const int wm   = (wid & 1) * 32;
    const int wn   = (wid >> 1) * (NT * 8);
    const int NTOT = NT * 32;

    const uint32_t* Ht  = (const uint32_t*)(smem + OFF_H);
    uint32_t*       Htw = (uint32_t*)(smem + OFF_H);
    uint32_t*       Gt  = (uint32_t*)(smem + OFF_G);
    const float* sb1 = (const float*)(smem + OFF_B1S);
    const float* sb2 = (const float*)(smem + OFF_B2S);
    const float* swo = (const float*)(smem + OFF_WO);

    const __nv_bfloat16* Bsrc =
        (MODE == 0) ? g_W1Tb : (MODE == 1) ? g_W2Tb :
        (MODE == 2) ? g_W2b : g_W1b;

    // A staging for MODE 0 (own group; k32 chunk = 64 rows x 64B = 256 xfers)
    auto stageA = [&](int kc, uint32_t dstOff) {
        const __nv_bfloat16* Ag = g_Sb + (size_t)m0 * D + kc * 32;
        int row = tid >> 2, c = tid & 3;
        cpa16(sbase + dstOff + row * 80 + c * 16, Ag + (size_t)row * D + c * 8);
        asm volatile("cp.async.commit_group;" ::: "memory");
    };

    // in-loop stage of chunk kc (B + A-if-MODE0), ONE commit group
    auto stage = [&](int kc, int b) {
        const __nv_bfloat16* Bg = Bsrc + kc * 32;
        const uint32_t bdst = sbase + (b ? OFF_BB1 : OFF_BB0);
#pragma unroll
        for (int i = 0; i < NTOT / 64; i++) {
            int idx = tid + (i << 8);
            int row = idx >> 2, c = idx & 3;
            cpa16(bdst + row * 80 + c * 16, Bg + (size_t)row * D + c * 8);
        }
        if (MODE == 0) {
            const __nv_bfloat16* Ag = g_Sb + (size_t)m0 * D + kc * 32;
            const uint32_t adst = sbase + (b ? OFF_AB1 : OFF_AB0);
            int row = tid >> 2, c = tid & 3;
            cpa16(adst + row * 80 + c * 16, Ag + (size_t)row * D + c * 8);
        }
        asm volatile("cp.async.commit_group;" ::: "memory");
    };

    if (MODE == 0) {
        // barrier: kick/init writes to g_Sb visible before cp.async reads;
        // also releases the G region (A-staging overlay).
        __syncthreads();
        stageA(0, OFF_AB0);
        stageA(1, OFF_AB1);
    }

    float acc[2][NT][4];
#pragma unroll
    for (int f = 0; f < 2; f++)
#pragma unroll
        for (int nf = 0; nf < NT; nf++)
#pragma unroll
            for (int r = 0; r < 4; r++) acc[f][nf][r] = 0.0f;

    // ldmatrix per-lane bases (staged 80B-row buffers)
    const uint32_t aStOff =
        (uint32_t)(wm + (lane & 15)) * 80 + ((lane >> 4) << 4);
    const uint32_t bStOff =
        (uint32_t)(wn + ((lane >> 4) << 3) + (lane & 7)) * 80 +
        (((lane >> 3) & 1) << 4);
    const int hi4w = (lane >> 4) << 2;          // 16B-half, words
    const int row7 = (lane & 7) << 2;           // tile swizzle bits
    uint32_t rrb[2];
#pragma unroll
    for (int f = 0; f < 2; f++)
        rrb[f] = sbase + ((MODE == 1) ? OFF_H : OFF_G) +
                 (uint32_t)(wm + f * 16 + (lane & 15)) * 512;

#pragma unroll 1
    for (int kc = 0; kc < 8; kc++) {
        const int b = kc & 1;
        if (kc < 7) asm volatile("cp.async.wait_group 1;" ::: "memory");
        else        asm volatile("cp.async.wait_group 0;" ::: "memory");
        __syncthreads();

        const uint32_t aSt = sbase + (b ? OFF_AB1 : OFF_AB0) + aStOff;
        const uint32_t bSt = sbase + (b ? OFF_BB1 : OFF_BB0) + bStOff;

#pragma unroll
        for (int kk = 0; kk < 2; kk++) {
            const int kg = kc * 2 + kk;
            uint32_t a[2][4], bb[NT][2];
            if (MODE == 0) {
                const uint32_t ab = aSt + kk * 32;
#pragma unroll
                for (int f = 0; f < 2; f++) LDMX4(a[f], ab + f * 1280);
            } else {
                const uint32_t s4 = (uint32_t)((((kg << 3) + hi4w) ^ row7) << 2);
#pragma unroll
                for (int f = 0; f < 2; f++) LDMX4(a[f], rrb[f] + s4);
            }
#pragma unroll
            for (int j = 0; j < NT / 2; j++) {
                uint32_t r[4];
                LDMX4(r, bSt + j * 1280 + kk * 32);
                bb[2*j][0]   = r[0];  bb[2*j][1]   = r[1];
                bb[2*j+1][0] = r[2];  bb[2*j+1][1] = r[3];
            }
#pragma unroll
            for (int f = 0; f < 2; f++)
#pragma unroll
                for (int nf = 0; nf < NT; nf++)
                    mma16(acc[f][nf], a[f], bb[nf]);
        }
        __syncthreads();
        if (kc + 2 < 8) stage(kc + 2, b);
    }

    // cross-pass prefetch: next pass's B chunks 0,1 (weights only — safe);
    // BB buffers free (all warps passed kc=7 post-compute barrier).
    if (nextB) {
        stageB_rows(sbase, OFF_BB0, nextB, 0, nextRows, tid);
        stageB_rows(sbase, OFF_BB1, nextB, 1, nextRows, tid);
    }

    // ------------------------------ epilogue --------------------------------
#pragma unroll
    for (int f = 0; f < 2; f++) {
        const int r = wm + f * 16 + g;           // local row; r&7 == g
#pragma unroll
        for (int nf = 0; nf < NT; nf++) {
            const int nc = wn + nf * 8 + 2 * t;
            const int ws = (nc >> 1) ^ (g << 2);
            float c0 = acc[f][nf][0], c1 = acc[f][nf][1];
            float c2 = acc[f][nf][2], c3 = acc[f][nf][3];

            if (MODE == 0) {
                float bv0 = sb1[nc], bv1 = sb1[nc + 1];
                Htw[r * 128 + ws]       = pk2(ftanh(c0 + bv0), ftanh(c1 + bv1));
                Htw[(r + 8) * 128 + ws] = pk2(ftanh(c2 + bv0), ftanh(c3 + bv1));
            } else if (MODE == 1) {
                float bv0 = sb2[nc], bv1 = sb2[nc + 1];
                float wv0 = swo[nc], wv1 = swo[nc + 1];
                float t0 = ftanh(c0 + bv0), t1 = ftanh(c1 + bv1);
                float t2 = ftanh(c2 + bv0), t3 = ftanh(c3 + bv1);
                Gt[r * 128 + ws]       = pk2(wv0 * (1.0f - t0 * t0),
                                             wv1 * (1.0f - t1 * t1));
                Gt[(r + 8) * 128 + ws] = pk2(wv0 * (1.0f - t2 * t2),
                                             wv1 * (1.0f - t3 * t3));
            } else if (MODE == 2) {
                float2 h0 = up2(Ht[r * 128 + ws]);
                float2 h1 = up2(Ht[(r + 8) * 128 + ws]);
                Gt[r * 128 + ws]       = pk2(c0 * (1.0f - h0.x * h0.x),
                                             c1 * (1.0f - h0.y * h0.y));
                Gt[(r + 8) * 128 + ws] = pk2(c2 * (1.0f - h1.x * h1.x),
                                             c3 * (1.0f - h1.y * h1.y));
            } else {
                const int grow = m0 + r;
                if (NT == 4 || nc < FD) {        // p -= 0.5*dt*dH[:, :FD]
                    float2* S0 = (float2*)(g_S + (size_t)grow * D + FD + nc);
                    float2* S1 = (float2*)(g_S + (size_t)(grow + 8) * D + FD + nc);
                    float2 p0 = *S0, p1 = *S1;
                    p0.x -= 0.5f * dtv * c0;  p0.y -= 0.5f * dtv * c1;
                    p1.x -= 0.5f * dtv * c2;  p1.y -= 0.5f * dtv * c3;
                    *S0 = p0;  *S1 = p1;
                    *(uint32_t*)(g_Sb + (size_t)grow * D + FD + nc)       = pk2(p0.x, p0.y);
                    *(uint32_t*)(g_Sb + (size_t)(grow + 8) * D + FD + nc) = pk2(p1.x, p1.y);
                } else {                          // q += dt*dH[:, FD:]
                    const int qc = nc - FD;
                    float2* S0 = (float2*)(g_S + (size_t)grow * D + qc);
                    float2* S1 = (float2*)(g_S + (size_t)(grow + 8) * D + qc);
                    float2 q0 = *S0, q1 = *S1;
                    q0.x += dtv * c0;  q0.y += dtv * c1;
                    q1.x += dtv * c2;  q1.y += dtv * c3;
                    *S0 = q0;  *S1 = q1;
                    *(uint32_t*)(g_Sb + (size_t)grow * D + qc)       = pk2(q0.x, q0.y);
                    *(uint32_t*)(g_Sb + (size_t)(grow + 8) * D + qc) = pk2(q1.x, q1.y);
                }
            }
        }
    }
    // no trailing barrier: MODE 1/2/3 passes begin with a post-wait
    // __syncthreads before any tile read; MODE 0 has its own entry barrier.
}

// ------------------------------ fused kernel --------------------------------
__global__ void __launch_bounds__(NTH, 2)
fused_kernel(const float* __restrict__ b1, const float* __restrict__ b2,
             const float* __restrict__ wo, const float* __restrict__ x,
             float* __restrict__ out) {
    extern __shared__ __align__(1024) char smem[];
    const uint32_t sbase = smem_u32(smem);
    const int tid = threadIdx.x;
    const int m0  = blockIdx.x * BM;
    const int bwd = (m0 >= BHALF);
    const int b0  = m0 & (BHALF - 1);

    // prefetch first pass's B chunks immediately (overlaps init below)
    stageB_rows(sbase, OFF_BB0, g_W1Tb, 0, 256, tid);
    stageB_rows(sbase, OFF_BB1, g_W1Tb, 1, 256, tid);

    ((float*)(smem + OFF_B1S))[tid] = b1[tid];
    ((float*)(smem + OFF_B2S))[tid] = b2[tid];
    ((float*)(smem + OFF_WO))[tid]  = wo[tid];

    // init this CTA's 64 state rows from x (row-private)
    for (int i = tid; i < BM * 128; i += NTH) {
        int r = i >> 7, f = i & 127;
        size_t xb = (size_t)(b0 + r) * 8192;
        float xm  = x[xb + 4096 + f];
        float xm1 = x[xb + 3968 + f];
        float q = xm, p = xm - xm1;
        size_t srow = (size_t)(m0 + r) * D;
        g_S[srow + f]      = q;
        g_S[srow + FD + f] = p;
        g_Sb[srow + f]      = __float2bfloat16(q);
        g_Sb[srow + FD + f] = __float2bfloat16(p);
    }
    // (MODE 0's entry barrier orders these writes before A staging)

    const float dtv = bwd ? -DT_MAG : DT_MAG;

#pragma unroll 1
    for (int it = 0; it < 8; it++) {
        pass_gemm<0, 8>(smem, sbase, m0, dtv, g_W2Tb, 256);
        pass_gemm<1, 8>(smem, sbase, m0, dtv, g_W2b, 256);
        if ((it & 1) == 0) {
            pass_gemm<2, 8>(smem, sbase, m0, dtv, g_W1b, 256);
            pass_gemm<3, 8>(smem, sbase, m0, dtv, g_W1Tb, 256);
        } else {
            pass_gemm<2, 8>(smem, sbase, m0, dtv, g_W1b, 128);
            if (it < 7) pass_gemm<4, 4>(smem, sbase, m0, dtv, g_W1Tb, 256);
            else        pass_gemm<4, 4>(smem, sbase, m0, dtv, nullptr, 0);
        }
    }

    // output: this CTA's rows -> disjoint column ranges of out
    __syncthreads();   // kick-epilogue g_S writes visible to all threads
    for (int i = tid; i < BM * 64; i += NTH) {
        int r = i >> 6, c4 = i & 63;
        float4 v = *(const float4*)(g_S + (size_t)(m0 + r) * D + c4 * 4);
        float* orow = out + (size_t)(b0 + r) * 768;
        if (bwd) *(float4*)(orow + c4 * 4) = v;          // [q_b | p_b]
        else     *(float4*)(orow + 512 + c4 * 4) = v;    // [q_f | p_f]
    }
    if (!bwd) {
        for (int i = tid; i < BM * 128; i += NTH) {
            int r = i >> 7, f = i & 127;
            size_t xb = (size_t)(b0 + r) * 8192;
            float xm  = x[xb + 4096 + f];
            float xm1 = x[xb + 3968 + f];
            float* orow = out + (size_t)(b0 + r) * 768;
            orow[256 + f] = xm;          // q_mid
            orow[384 + f] = xm - xm1;    // p_mid
        }
    }
}

// ---------------------------------------------------------------------------
extern "C" void kernel_launch(void* const* d_in, const int* in_sizes, int n_in,
                              void* d_out, int out_size) {
    const float* x    = (const float*)d_in[0];
    const float* W1   = (const float*)d_in[1];
    const float* b1   = (const float*)d_in[2];
    const float* W2   = (const float*)d_in[3];
    const float* b2   = (const float*)d_in[4];
    const float* Wout = (const float*)d_in[5];
    float* out = (float*)d_out;

    cudaFuncSetAttribute(fused_kernel,
                         cudaFuncAttributeMaxDynamicSharedMemorySize, SMEM_TOTAL);

    prep_kernel<<<D * D / 256, 256>>>(W1, W2);
    fused_kernel<<<MTOT / BM, NTH, SMEM_TOTAL>>>(b1, b2, Wout, x, out);
}

// round 10
// speedup vs baseline: 1.1981x; 1.1981x over previous
#include <cuda_runtime.h>
#include <cuda_bf16.h>
#include <math.h>
#include <cstdint>

// ============================================================================
// BiDirectionalSymplecticLayer — fused persistent kernel, 3-buffer edition.
// BM=128 rows/CTA, 512 threads. All 8 gradient evals run locally; H/G tiles
// resident in swizzled smem; weights stream L2->smem in k64 chunks through a
// 3-deep single-barrier cp.async pipeline (swizzled 128B rows). ldmatrix
// fragments; cross-pass weight prefetch; MUFU-lite tanh (1 MUFU + FMA Newton).
// ============================================================================

#define D       256
#define FD      128
#define MTOT    16384
#define BHALF   8192
#define DT_MAG  0.1f
#define BM      128
#define NTH     512

// smem layout (bytes)
#define OFF_H   0                        // H tile: 128 rows x 512B, swizzled
#define OFF_G   65536                    // G tile; A bufs overlay in MODE 0
#define OFF_A0  65536                    // A staging: 3 x (128 x 128B)
#define OFF_B0  131072                   // B staging: 3 x (256 x 128B)
#define ABUF_SZ 16384
#define BBUF_SZ 32768
#define SMEM_TOTAL (131072 + 3 * BBUF_SZ)   // 229376

__device__ float         g_S [MTOT * D];
__device__ __nv_bfloat16 g_Sb[MTOT * D];
__device__ __nv_bfloat16 g_W1b [D * D];    // W1  [n][k]
__device__ __nv_bfloat16 g_W2b [D * D];    // W2  [n][k]
__device__ __nv_bfloat16 g_W1Tb[D * D];    // W1^T [n][k]
__device__ __nv_bfloat16 g_W2Tb[D * D];    // W2^T [n][k]

// ------------------------------- helpers ------------------------------------
__device__ __forceinline__ void cpa16(uint32_t dst, const void* src) {
    asm volatile("cp.async.cg.shared.global [%0], [%1], 16;"
                 :: "r"(dst), "l"(src) : "memory");
}
__device__ __forceinline__ uint32_t smem_u32(const void* p) {
    uint32_t r;
    asm("{ .reg .u64 t; cvta.to.shared.u64 t, %1; cvt.u32.u64 %0, t; }"
        : "=r"(r) : "l"(p));
    return r;
}
__device__ __forceinline__ void mma16(float* c, const uint32_t* a, const uint32_t* b) {
    asm volatile(
        "mma.sync.aligned.m16n8k16.row.col.f32.bf16.bf16.f32 "
        "{%0,%1,%2,%3}, {%4,%5,%6,%7}, {%8,%9}, {%0,%1,%2,%3};"
        : "+f"(c[0]), "+f"(c[1]), "+f"(c[2]), "+f"(c[3])
        : "r"(a[0]), "r"(a[1]), "r"(a[2]), "r"(a[3]), "r"(b[0]), "r"(b[1]));
}
#define LDMX4(r, addr) \
    asm volatile("ldmatrix.sync.aligned.m8n8.x4.shared.b16 {%0,%1,%2,%3}, [%4];" \
                 : "=r"((r)[0]), "=r"((r)[1]), "=r"((r)[2]), "=r"((r)[3]) \
                 : "r"(addr))
__device__ __forceinline__ uint32_t pk2(float x, float y) {
    __nv_bfloat162 h = __floats2bfloat162_rn(x, y);
    return *reinterpret_cast<uint32_t*>(&h);
}
__device__ __forceinline__ float2 up2(uint32_t u) {
    __nv_bfloat162 h = *reinterpret_cast<__nv_bfloat162*>(&u);
    return make_float2(__bfloat162float(h.x), __bfloat162float(h.y));
}
// tanh = 1 - 2/(1+e^{2x}); reciprocal via bit-trick + 2 Newton steps (FMA pipe)
// -> 1 MUFU per tanh instead of 2. abs err ~6e-6 << bf16 ulp.
__device__ __forceinline__ float ftanh(float x) {
    x = fminf(20.0f, fmaxf(-20.0f, x));
    float e;
    asm("ex2.approx.f32 %0, %1;" : "=f"(e) : "f"(x * 2.885390082f));
    float d = e + 1.0f;
    float y = __int_as_float(0x7EF311C3 - __float_as_int(d));
    y = y * (2.0f - d * y);
    y = y * (2.0f - d * y);
    return 1.0f - 2.0f * y;
}

// stage one k64 B chunk (rows x 128B) into a swizzled buffer; own group.
__device__ __forceinline__ void stageB_rows(uint32_t dst, const __nv_bfloat16* Bg0,
                                            int kc, int rows, int tid) {
    const __nv_bfloat16* Bg = Bg0 + kc * 64;
    const int n = rows >> 6;                  // rows*8 xfers / 512 threads
    for (int i = 0; i < n; i++) {
        int idx = tid + (i << 9);
        int row = idx >> 3, c = idx & 7;
        cpa16(dst + row * 128 + ((c ^ (row & 7)) << 4),
              Bg + (size_t)row * D + c * 8);
    }
    asm volatile("cp.async.commit_group;" ::: "memory");
}

// --------------------------- prologue kernel --------------------------------
__global__ void prep_kernel(const float* __restrict__ W1,
                            const float* __restrict__ W2) {
    int idx = blockIdx.x * blockDim.x + threadIdx.x;
    int r = idx >> 8, c = idx & 255;
    __nv_bfloat16 v1 = __float2bfloat16(W1[idx]);
    __nv_bfloat16 v2 = __float2bfloat16(W2[idx]);
    g_W1b[idx] = v1;
    g_W2b[idx] = v2;
    g_W1Tb[c * D + r] = v1;
    g_W2Tb[c * D + r] = v2;
}

// ------------------------------ fused pass ----------------------------------
//  MODE 0: A = staged g_Sb, B = g_W1Tb -> H = tanh(acc + b1)
//  MODE 1: A = H tile,      B = g_W2Tb -> G = wout*(1 - tanh(acc+b2)^2)
//  MODE 2: A = G tile,      B = g_W2b  -> G = acc*(1 - H^2)   (in place)
//  MODE 3: A = G tile,      B = g_W1b  -> full kick (NT=8)
//  MODE 4: A = G tile,      B = g_W1b  -> half kick (NT=4)
// 3-buffer pipeline, buffer-start index bs rotates +1 per pass (4 chunks mod 3).
template <int MODE, int NT>
__device__ __forceinline__ void pass_gemm(char* smem, uint32_t sbase,
                                          int m0, float dtv, int bs,
                                          const __nv_bfloat16* nextB, int nextRows,
                                          const float* __restrict__ b1g,
                                          const float* __restrict__ b2g,
                                          const float* __restrict__ wog) {
    const int tid  = threadIdx.x;
    const int wid  = tid >> 5;
    const int lane = tid & 31;
    const int g    = lane >> 2;
    const int t    = lane & 3;
    const int wm   = (wid & 3) * 32;
    const int wn   = (wid >> 2) * (NT * 8);
    const int NTOT = NT * 32;

    const uint32_t* Ht  = (const uint32_t*)(smem + OFF_H);
    uint32_t*       Htw = (uint32_t*)(smem + OFF_H);
    uint32_t*       Gt  = (uint32_t*)(smem + OFF_G);

    const __nv_bfloat16* Bsrc =
        (MODE == 0) ? g_W1Tb : (MODE == 1) ? g_W2Tb :
        (MODE == 2) ? g_W2b : g_W1b;

    const uint32_t Bbase = sbase + OFF_B0;
    const uint32_t Abase = sbase + OFF_A0;
    auto rotB = [&](uint32_t v) { return (v == Bbase + 2 * BBUF_SZ) ? Bbase : v + BBUF_SZ; };
    auto rotA = [&](uint32_t v) { return (v == Abase + 2 * ABUF_SZ) ? Abase : v + ABUF_SZ; };

    uint32_t curB = Bbase + (uint32_t)bs * BBUF_SZ;   // buffer of chunk kc
    uint32_t curA = Abase + (uint32_t)bs * ABUF_SZ;
    uint32_t stgB = rotB(rotB(curB));                 // buffer of chunk kc+2
    uint32_t stgA = rotA(rotA(curA));

    // stage chunk kc (B + A-if-MODE0), ONE commit group
    auto stage = [&](int kc, uint32_t bdst, uint32_t adst) {
        const __nv_bfloat16* Bg = Bsrc + kc * 64;
#pragma unroll
        for (int i = 0; i < NTOT / 64; i++) {
            int idx = tid + (i << 9);
            int row = idx >> 3, c = idx & 7;
            cpa16(bdst + row * 128 + ((c ^ (row & 7)) << 4),
                  Bg + (size_t)row * D + c * 8);
        }
        if (MODE == 0) {
            const __nv_bfloat16* Ag = g_Sb + (size_t)m0 * D + kc * 64;
#pragma unroll
            for (int i = 0; i < 2; i++) {
                int idx = tid + (i << 9);
                int row = idx >> 3, c = idx & 7;
                cpa16(adst + row * 128 + ((c ^ (row & 7)) << 4),
                      Ag + (size_t)row * D + c * 8);
            }
        }
        asm volatile("cp.async.commit_group;" ::: "memory");
    };
    auto stageA1 = [&](int kc, uint32_t adst) {       // A only, own group
        const __nv_bfloat16* Ag = g_Sb + (size_t)m0 * D + kc * 64;
#pragma unroll
        for (int i = 0; i < 2; i++) {
            int idx = tid + (i << 9);
            int row = idx >> 3, c = idx & 7;
            cpa16(adst + row * 128 + ((c ^ (row & 7)) << 4),
                  Ag + (size_t)row * D + c * 8);
        }
        asm volatile("cp.async.commit_group;" ::: "memory");
    };

    if (MODE == 0) {
        // order prior kick/init writes to g_Sb before cp.async reads; also
        // releases the G region (A-staging overlay).
        __syncthreads();
        stageA1(0, curA);
        stageA1(1, rotA(curA));
    }

    float acc[2][NT][4];
#pragma unroll
    for (int f = 0; f < 2; f++)
#pragma unroll
        for (int nf = 0; nf < NT; nf++)
#pragma unroll
            for (int r = 0; r < 4; r++) acc[f][nf][r] = 0.0f;

    // per-lane fragment address pieces
    const uint32_t aRowB = (uint32_t)(wm + (lane & 15)) * 128;  // staged A
    const int      ax7   = lane & 7;
    const int      akh   = lane >> 4;
    const uint32_t bRowB =
        (uint32_t)(wn + ((lane >> 4) << 3) + (lane & 7)) * 128; // staged B
    const int      bx7   = (wn + ((lane >> 4) << 3) + (lane & 7)) & 7;
    const int      bkh   = (lane >> 3) & 1;
    const int hi4w = (lane >> 4) << 2;          // resident tiles
    const int row7 = (lane & 7) << 2;
    uint32_t rrb[2];
#pragma unroll
    for (int f = 0; f < 2; f++)
        rrb[f] = sbase + ((MODE == 1) ? OFF_H : OFF_G) +
                 (uint32_t)(wm + f * 16 + (lane & 15)) * 512;

#pragma unroll 1
    for (int kc = 0; kc < 4; kc++) {
        if (kc < 3) asm volatile("cp.async.wait_group 1;" ::: "memory");
        else        asm volatile("cp.async.wait_group 0;" ::: "memory");
        __syncthreads();
        if (kc < 2) stage(kc + 2, stgB, stgA);   // safe: all warps past barrier

        const uint32_t aB = curA + aRowB;
        const uint32_t bB = curB + bRowB;

#pragma unroll
        for (int kk = 0; kk < 4; kk++) {
            const int kg = kc * 4 + kk;
            uint32_t a[2][4], bb[NT][2];
            if (MODE == 0) {
                const uint32_t sa = (uint32_t)((((kk << 1) + akh) ^ ax7) << 4);
#pragma unroll
                for (int f = 0; f < 2; f++) LDMX4(a[f], aB + f * 2048 + sa);
            } else {
                const uint32_t s4 = (uint32_t)((((kg << 3) + hi4w) ^ row7) << 2);
#pragma unroll
                for (int f = 0; f < 2; f++) LDMX4(a[f], rrb[f] + s4);
            }
            const uint32_t sb4 = (uint32_t)((((kk << 1) + bkh) ^ bx7) << 4);
#pragma unroll
            for (int j = 0; j < NT / 2; j++) {
                uint32_t r[4];
                LDMX4(r, bB + j * 2048 + sb4);
                bb[2*j][0]   = r[0];  bb[2*j][1]   = r[1];
                bb[2*j+1][0] = r[2];  bb[2*j+1][1] = r[3];
            }
#pragma unroll
            for (int f = 0; f < 2; f++)
#pragma unroll
                for (int nf = 0; nf < NT; nf++)
                    mma16(acc[f][nf], a[f], bb[nf]);
        }
        curB = rotB(curB);  curA = rotA(curA);
        stgB = rotB(stgB);  stgA = rotA(stgA);
    }

    // cross-pass prefetch: next pass (bs+1) uses bufs bs+1, bs+2 for chunks
    // 0,1 — curB has rotated 4 times == bs+1. Clobber-free: stragglers only
    // hold buf bs (their kc=3 chunk).
    if (nextB) {
        stageB_rows(curB, nextB, 0, nextRows, tid);
        stageB_rows(rotB(curB), nextB, 1, nextRows, tid);
    }
    if (MODE == 2) __syncthreads();   // in-place G overwrite needs all reads done

    // ------------------------------ epilogue --------------------------------
#pragma unroll
    for (int f = 0; f < 2; f++) {
        const int r = wm + f * 16 + g;           // local row; r&7 == g
#pragma unroll
        for (int nf = 0; nf < NT; nf++) {
            const int nc = wn + nf * 8 + 2 * t;
            const int ws = (nc >> 1) ^ (g << 2);
            float c0 = acc[f][nf][0], c1 = acc[f][nf][1];
            float c2 = acc[f][nf][2], c3 = acc[f][nf][3];

            if (MODE == 0) {
                float bv0 = __ldg(b1g + nc), bv1 = __ldg(b1g + nc + 1);
                Htw[r * 128 + ws]       = pk2(ftanh(c0 + bv0), ftanh(c1 + bv1));
                Htw[(r + 8) * 128 + ws] = pk2(ftanh(c2 + bv0), ftanh(c3 + bv1));
            } else if (MODE == 1) {
                float bv0 = __ldg(b2g + nc), bv1 = __ldg(b2g + nc + 1);
                float wv0 = __ldg(wog + nc), wv1 = __ldg(wog + nc + 1);
                float t0 = ftanh(c0 + bv0), t1 = ftanh(c1 + bv1);
                float t2 = ftanh(c2 + bv0), t3 = ftanh(c3 + bv1);
                Gt[r * 128 + ws]       = pk2(wv0 * (1.0f - t0 * t0),
                                             wv1 * (1.0f - t1 * t1));
                Gt[(r + 8) * 128 + ws] = pk2(wv0 * (1.0f - t2 * t2),
                                             wv1 * (1.0f - t3 * t3));
            } else if (MODE == 2) {
                float2 h0 = up2(Ht[r * 128 + ws]);
                float2 h1 = up2(Ht[(r + 8) * 128 + ws]);
                Gt[r * 128 + ws]       = pk2(c0 * (1.0f - h0.x * h0.x),
                                             c1 * (1.0f - h0.y * h0.y));
                Gt[(r + 8) * 128 + ws] = pk2(c2 * (1.0f - h1.x * h1.x),
                                             c3 * (1.0f - h1.y * h1.y));
            } else {
                const int grow = m0 + r;
                if (NT == 4 || nc < FD) {        // p -= 0.5*dt*dH[:, :FD]
                    float2* S0 = (float2*)(g_S + (size_t)grow * D + FD + nc);
                    float2* S1 = (float2*)(g_S + (size_t)(grow + 8) * D + FD + nc);
                    float2 p0 = *S0, p1 = *S1;
                    p0.x -= 0.5f * dtv * c0;  p0.y -= 0.5f * dtv * c1;
                    p1.x -= 0.5f * dtv * c2;  p1.y -= 0.5f * dtv * c3;
                    *S0 = p0;  *S1 = p1;
                    *(uint32_t*)(g_Sb + (size_t)grow * D + FD + nc)       = pk2(p0.x, p0.y);
                    *(uint32_t*)(g_Sb + (size_t)(grow + 8) * D + FD + nc) = pk2(p1.x, p1.y);
                } else {                          // q += dt*dH[:, FD:]
                    const int qc = nc - FD;
                    float2* S0 = (float2*)(g_S + (size_t)grow * D + qc);
                    float2* S1 = (float2*)(g_S + (size_t)(grow + 8) * D + qc);
                    float2 q0 = *S0, q1 = *S1;
                    q0.x += dtv * c0;  q0.y += dtv * c1;
                    q1.x += dtv * c2;  q1.y += dtv * c3;
                    *S0 = q0;  *S1 = q1;
                    *(uint32_t*)(g_Sb + (size_t)grow * D + qc)       = pk2(q0.x, q0.y);
                    *(uint32_t*)(g_Sb + (size_t)(grow + 8) * D + qc) = pk2(q1.x, q1.y);
                }
            }
        }
    }
    // no trailing barrier: every pass begins with wait+__syncthreads before
    // any staged-buffer or tile read; MODE 0/2 carry their extra barriers.
}

// ------------------------------ fused kernel --------------------------------
__global__ void __launch_bounds__(NTH, 1)
fused_kernel(const float* __restrict__ b1, const float* __restrict__ b2,
             const float* __restrict__ wo, const float* __restrict__ x,
             float* __restrict__ out) {
    extern __shared__ __align__(1024) char smem[];
    const uint32_t sbase = smem_u32(smem);
    const int tid = threadIdx.x;
    const int m0  = blockIdx.x * BM;
    const int bwd = (m0 >= BHALF);
    const int b0  = m0 & (BHALF - 1);

    // prefetch first pass's B chunks (bufs 0,1) — overlaps init below
    stageB_rows(sbase + OFF_B0, g_W1Tb, 0, 256, tid);
    stageB_rows(sbase + OFF_B0 + BBUF_SZ, g_W1Tb, 1, 256, tid);

    // init this CTA's 128 state rows from x (row-private)
    for (int i = tid; i < BM * 128; i += NTH) {
        int r = i >> 7, f = i & 127;
        size_t xb = (size_t)(b0 + r) * 8192;
        float xm  = x[xb + 4096 + f];
        float xm1 = x[xb + 3968 + f];
        float q = xm, p = xm - xm1;
        size_t srow = (size_t)(m0 + r) * D;
        g_S[srow + f]      = q;
        g_S[srow + FD + f] = p;
        g_Sb[srow + f]      = __float2bfloat16(q);
        g_Sb[srow + FD + f] = __float2bfloat16(p);
    }
    // (MODE 0's entry barrier orders these writes before A staging)

    const float dtv = bwd ? -DT_MAG : DT_MAG;
    int bs = 0;
    auto inc = [&]() { bs = (bs == 2) ? 0 : bs + 1; };

#pragma unroll 1
    for (int it = 0; it < 8; it++) {
        pass_gemm<0, 8>(smem, sbase, m0, dtv, bs, g_W2Tb, 256, b1, b2, wo); inc();
        pass_gemm<1, 8>(smem, sbase, m0, dtv, bs, g_W2b, 256, b1, b2, wo);  inc();
        if ((it & 1) == 0) {
            pass_gemm<2, 8>(smem, sbase, m0, dtv, bs, g_W1b, 256, b1, b2, wo); inc();
            pass_gemm<3, 8>(smem, sbase, m0, dtv, bs, g_W1Tb, 256, b1, b2, wo); inc();
        } else {
            pass_gemm<2, 8>(smem, sbase, m0, dtv, bs, g_W1b, 128, b1, b2, wo); inc();
            if (it < 7) { pass_gemm<4, 4>(smem, sbase, m0, dtv, bs, g_W1Tb, 256, b1, b2, wo); }
            else        { pass_gemm<4, 4>(smem, sbase, m0, dtv, bs, nullptr, 0, b1, b2, wo); }
            inc();
        }
    }

    // output: this CTA's rows -> disjoint column ranges of out
    __syncthreads();   // kick-epilogue g_S writes visible to all threads
    for (int i = tid; i < BM * 64; i += NTH) {
        int r = i >> 6, c4 = i & 63;
        float4 v = *(const float4*)(g_S + (size_t)(m0 + r) * D + c4 * 4);
        float* orow = out + (size_t)(b0 + r) * 768;
        if (bwd) *(float4*)(orow + c4 * 4) = v;          // [q_b | p_b]
        else     *(float4*)(orow + 512 + c4 * 4) = v;    // [q_f | p_f]
    }
    if (!bwd) {
        for (int i = tid; i < BM * 128; i += NTH) {
            int r = i >> 7, f = i & 127;
            size_t xb = (size_t)(b0 + r) * 8192;
            float xm  = x[xb + 4096 + f];
            float xm1 = x[xb + 3968 + f];
            float* orow = out + (size_t)(b0 + r) * 768;
            orow[256 + f] = xm;          // q_mid
            orow[384 + f] = xm - xm1;    // p_mid
        }
    }
}

// ---------------------------------------------------------------------------
extern "C" void kernel_launch(void* const* d_in, const int* in_sizes, int n_in,
                              void* d_out, int out_size) {
    const float* x    = (const float*)d_in[0];
    const float* W1   = (const float*)d_in[1];
    const float* b1   = (const float*)d_in[2];
    const float* W2   = (const float*)d_in[3];
    const float* b2   = (const float*)d_in[4];
    const float* Wout = (const float*)d_in[5];
    float* out = (float*)d_out;

    cudaFuncSetAttribute(fused_kernel,
                         cudaFuncAttributeMaxDynamicSharedMemorySize, SMEM_TOTAL);

    prep_kernel<<<D * D / 256, 256>>>(W1, W2);
    fused_kernel<<<MTOT / BM, NTH, SMEM_TOTAL>>>(b1, b2, Wout, x, out);
}